// round 16
// baseline (speedup 1.0000x reference)
#include <cuda_runtime.h>
#include <cuda_fp16.h>
#include <cstdlib>

// Problem constants (from setup_inputs)
#define MAX_N 50000
#define MAX_E 800000
#define DIM   64
#define SCAN_T 512

// ---------------------------------------------------------------------------
// Globals ~10.2 MB total (known-good; ~17 MB trips the harness memory guard).
// g_dis / g_fill are zero on first call (module zero-init) and reset to zero
// by gather2f's tail every call -> identical state for every graph replay.
// g_zh is reused three times per call: xh (xprep) -> consumed by agg1f,
// then zhat (gemm) -> consumed by gather2f. Kernel boundaries order it.
__device__ float  g_dis[MAX_N];          // edge-indegree (float) -> rsqrt(deg+1)
__device__ int    g_start[MAX_N + 1];    // CSR row offsets
__device__ int    g_fill[MAX_N];         // counts, then atomic fill cursors
__device__ int    g_col[MAX_E];          // CSR column indices       (3.2 MB)
__device__ __half g_zh[MAX_N * DIM];     // fp16 stage buffer        (6.4 MB)
__device__ int    g_bsum[128];           // scan block sums (nblk <= 98)

namespace {  // harmless; default-priority (allowed)
struct EagerEnv { EagerEnv() { setenv("CUDA_MODULE_LOADING", "EAGER", 1); } };
EagerEnv _eager_env_instance;
}

// ---------------------------------------------------------------------------
// 1) count: out-count of row (CSR buckets) + edge-indegree of col.
// Edges are int32 (JAX x64-disabled; verified across R9-R15 passing runs).
__global__ void count_kernel(const int* __restrict__ ei, int E) {
    int i = blockIdx.x * blockDim.x + threadIdx.x;
    if (i < E) {
        int r = ei[i];
        int c = ei[E + i];
        atomicAdd(&g_fill[r], 1);
        atomicAdd(&g_dis[c], 1.0f);   // float counts exact (< 2^24)
    }
}

// block inclusive scan helper (any block size that's a multiple of 32; uses
// warp_sums[32] shared scratch)
__device__ __forceinline__ int block_incl_scan(int v, int* warp_sums) {
    int lane = threadIdx.x & 31, wid = threadIdx.x >> 5;
    int nw = blockDim.x >> 5;
    int x = v;
    #pragma unroll
    for (int off = 1; off < 32; off <<= 1) {
        int t = __shfl_up_sync(0xffffffffu, x, off);
        if (lane >= off) x += t;
    }
    if (lane == 31) warp_sums[wid] = x;
    __syncthreads();
    if (wid == 0) {
        int ws = (lane < nw) ? warp_sums[lane] : 0;
        #pragma unroll
        for (int off = 1; off < 32; off <<= 1) {
            int t = __shfl_up_sync(0xffffffffu, ws, off);
            if (lane >= off) ws += t;
        }
        warp_sums[lane] = ws;
    }
    __syncthreads();
    return x + (wid > 0 ? warp_sums[wid - 1] : 0);
}

// 2a) per-block exclusive scan of counts; block total -> g_bsum;
//     dis = rsqrt(edge_indegree + 1)   (the +1 is the self loop)
__global__ void scanA_kernel(int n) {
    __shared__ int warp_sums[32];
    int i = blockIdx.x * SCAN_T + threadIdx.x;
    int v = 0;
    if (i < n) {
        v = g_fill[i];
        g_dis[i] = rsqrtf(g_dis[i] + 1.0f);
    }
    int incl = block_incl_scan(v, warp_sums);
    if (i < n) g_start[i] = incl - v;            // local exclusive
    if (threadIdx.x == SCAN_T - 1) g_bsum[blockIdx.x] = incl;
}

// 2b) add block offsets (PARALLEL prefix of <=98 block sums, redundantly per
//     block); init fill cursors; total at g_start[n]
__global__ void scanC_kernel(int n, int nblk) {
    __shared__ int warp_sums[32];
    __shared__ int sboff[256 + 1];
    int tid = threadIdx.x;
    {
        int v = (tid < nblk) ? g_bsum[tid] : 0;
        int incl = block_incl_scan(v, warp_sums);
        sboff[tid] = incl - v;                   // exclusive
        if (tid == nblk - 1) sboff[nblk] = incl; // total
    }
    __syncthreads();
    int i = blockIdx.x * blockDim.x + tid;
    if (i < n) {
        int s = g_start[i] + sboff[i / SCAN_T];
        g_start[i] = s;
        g_fill[i] = s;
    }
    if (i == 0) g_start[n] = sboff[nblk];
}

// 3) fill CSR columns
__global__ void fill_kernel(const int* __restrict__ ei, int E) {
    int i = blockIdx.x * blockDim.x + threadIdx.x;
    if (i < E) {
        int r = ei[i];
        int c = ei[E + i];
        int p = atomicAdd(&g_fill[r], 1);
        g_col[p] = c;
    }
}

// 4) xprep: xh = dis .* x as fp16 into g_zh. One half2 (2 features)/thread.
__global__ void xprep_kernel(const float* __restrict__ x, int n) {
    int t = blockIdx.x * blockDim.x + threadIdx.x;
    if (t >= n * 32) return;
    int r = t >> 5;
    float d = g_dis[r];
    float2 v = ((const float2*)x)[t];
    ((__half2*)g_zh)[t] = __floats2half2_rn(d * v.x, d * v.y);
}

// 5) layer-1 aggregation, pure fp16 row sum (pre-scaled inputs): warp per
//    node, half2 per lane, 8x unroll.
//    h[r] = dis_r * ( sum_{c in N(r)} xh_c + xh_r ),  xh_r = dis_r*x_r
//    Writes fp32 h to d_out (consumed by the GEMM).
__global__ void agg1f_kernel(float* __restrict__ out, int n) {
    int gw = (blockIdx.x * blockDim.x + threadIdx.x) >> 5;
    if (gw >= n) return;
    int lane = threadIdx.x & 31;
    const __half2* __restrict__ z2 = (const __half2*)g_zh;

    int e = g_start[gw];
    int end = g_start[gw + 1];
    float ax = 0.f, ay = 0.f;
    for (; e + 8 <= end; e += 8) {
        int c0 = g_col[e + 0], c1 = g_col[e + 1], c2 = g_col[e + 2], c3 = g_col[e + 3];
        int c4 = g_col[e + 4], c5 = g_col[e + 5], c6 = g_col[e + 6], c7 = g_col[e + 7];
        float2 v0 = __half22float2(z2[c0 * 32 + lane]);
        float2 v1 = __half22float2(z2[c1 * 32 + lane]);
        float2 v2 = __half22float2(z2[c2 * 32 + lane]);
        float2 v3 = __half22float2(z2[c3 * 32 + lane]);
        float2 v4 = __half22float2(z2[c4 * 32 + lane]);
        float2 v5 = __half22float2(z2[c5 * 32 + lane]);
        float2 v6 = __half22float2(z2[c6 * 32 + lane]);
        float2 v7 = __half22float2(z2[c7 * 32 + lane]);
        ax += (v0.x + v1.x) + (v2.x + v3.x);
        ay += (v0.y + v1.y) + (v2.y + v3.y);
        ax += (v4.x + v5.x) + (v6.x + v7.x);
        ay += (v4.y + v5.y) + (v6.y + v7.y);
    }
    for (; e < end; e++) {
        float2 v = __half22float2(z2[g_col[e] * 32 + lane]);
        ax += v.x;
        ay += v.y;
    }
    float2 sv = __half22float2(z2[gw * 32 + lane]);   // self loop (xh_r)
    ax += sv.x;
    ay += sv.y;
    float dr = g_dis[gw];
    ((float2*)out)[(long long)gw * 32 + lane] = make_float2(dr * ax, dr * ay);
}

// 6) mid GEMM with pre-scale, fp16 output: zhat[r] = dis_r * (h[r] @ W^T),
//    stored as __half2 into g_zh (xh already consumed by agg1f).
__global__ void gemm_sc_kernel(const float* __restrict__ h, const float* __restrict__ W,
                               int n) {
    __shared__ float Wt[64 * 64];  // Wt[k][nn] = W[nn][k]
    int tid = threadIdx.x;
    for (int t = tid; t < 64 * 64; t += blockDim.x) {
        int k = t >> 6, nn = t & 63;
        Wt[k * 64 + nn] = W[nn * 64 + k];
    }
    __syncthreads();

    int lane = tid & 31, wid = tid >> 5;
    int nwarps = blockDim.x >> 5;
    const float2* __restrict__ Wt2 = (const float2*)Wt;
    __half2* __restrict__ z2 = (__half2*)g_zh;

    for (int r = blockIdx.x * nwarps + wid; r < n; r += gridDim.x * nwarps) {
        float2 hv = ((const float2*)h)[r * 32 + lane];
        float a0 = 0.f, a1 = 0.f;
        #pragma unroll
        for (int k = 0; k < 64; k++) {
            float hk = __shfl_sync(0xffffffffu, (k & 1) ? hv.y : hv.x, k >> 1);
            float2 w = Wt2[k * 32 + lane];       // features 2*lane, 2*lane+1
            a0 = fmaf(hk, w.x, a0);
            a1 = fmaf(hk, w.y, a1);
        }
        float dr = g_dis[r];
        z2[r * 32 + lane] = __floats2half2_rn(dr * a0, dr * a1);
    }
}

// 7) FUSED layer-2 gather + bias + output: warp per node, half2 per lane,
//    8x unroll, pure row sum.  out[r] = dis_r*( sum_c zhat_c + zhat_r ) + b
//    Tail: reset g_dis[gw]/g_fill[gw] for the next graph replay.
__global__ void gather2f_kernel(const float* __restrict__ b, float* __restrict__ out,
                                int n) {
    int gw = (blockIdx.x * blockDim.x + threadIdx.x) >> 5;
    if (gw >= n) return;
    int lane = threadIdx.x & 31;
    const __half2* __restrict__ z2 = (const __half2*)g_zh;
    float2 bb = ((const float2*)b)[lane];        // bias for features 2l, 2l+1

    int e = g_start[gw];
    int end = g_start[gw + 1];
    float ax = 0.f, ay = 0.f;
    for (; e + 8 <= end; e += 8) {
        int c0 = g_col[e + 0], c1 = g_col[e + 1], c2 = g_col[e + 2], c3 = g_col[e + 3];
        int c4 = g_col[e + 4], c5 = g_col[e + 5], c6 = g_col[e + 6], c7 = g_col[e + 7];
        float2 v0 = __half22float2(z2[c0 * 32 + lane]);
        float2 v1 = __half22float2(z2[c1 * 32 + lane]);
        float2 v2 = __half22float2(z2[c2 * 32 + lane]);
        float2 v3 = __half22float2(z2[c3 * 32 + lane]);
        float2 v4 = __half22float2(z2[c4 * 32 + lane]);
        float2 v5 = __half22float2(z2[c5 * 32 + lane]);
        float2 v6 = __half22float2(z2[c6 * 32 + lane]);
        float2 v7 = __half22float2(z2[c7 * 32 + lane]);
        ax += (v0.x + v1.x) + (v2.x + v3.x);
        ay += (v0.y + v1.y) + (v2.y + v3.y);
        ax += (v4.x + v5.x) + (v6.x + v7.x);
        ay += (v4.y + v5.y) + (v6.y + v7.y);
    }
    for (; e < end; e++) {
        float2 v = __half22float2(z2[g_col[e] * 32 + lane]);
        ax += v.x;
        ay += v.y;
    }
    float2 sv = __half22float2(z2[gw * 32 + lane]);   // self loop
    ax += sv.x;
    ay += sv.y;
    float dr = g_dis[gw];
    ((float2*)out)[(long long)gw * 32 + lane] =
        make_float2(fmaf(dr, ax, bb.x), fmaf(dr, ay, bb.y));

    // reset per-call accumulated state for the next graph replay
    if (lane == 0) { g_dis[gw] = 0.0f; g_fill[gw] = 0; }
}

extern "C" void kernel_launch(void* const* d_in, const int* in_sizes, int n_in,
                              void* d_out, int out_size) {
    const float* x  = (const float*)d_in[0];
    const int*   ei = (const int*)d_in[1];     // int32 (verified empirically)
    const float* W  = (const float*)d_in[2];
    const float* b  = (const float*)d_in[3];
    float* out = (float*)d_out;

    int N = in_sizes[0] / DIM;   // 50000
    int E = in_sizes[1] / 2;     // 800000

    const int T = 256;
    int nb = (N + T - 1) / T;
    int eb = (E + T - 1) / T;
    int warp_blocks = (N * 32 + T - 1) / T;
    int nscan = (N + SCAN_T - 1) / SCAN_T;

    // CSR build (g_dis/g_fill arrive zeroed: module init call 1, gather2f tail after)
    count_kernel<<<eb, T>>>(ei, E);
    scanA_kernel<<<nscan, SCAN_T>>>(N);
    scanC_kernel<<<nb, T>>>(N, nscan);
    fill_kernel<<<eb, T>>>(ei, E);

    // xh(fp16) = dis .* x  -> g_zh
    xprep_kernel<<<warp_blocks, T>>>(x, N);

    // layer 1 (pure fp16 row sum): h = dis .* (rowsum xh) -> d_out (fp32)
    agg1f_kernel<<<warp_blocks, T>>>(out, N);

    // mid GEMM: zhat(fp16) = dis .* (h @ W^T) -> g_zh (overwrite)
    gemm_sc_kernel<<<296, 256>>>(out, W, N);

    // layer 2 fused: out = dis .* (rowsum zhat) + b
    gather2f_kernel<<<warp_blocks, T>>>(b, out, N);
}